// round 14
// baseline (speedup 1.0000x reference)
#include <cuda_runtime.h>
#include <math.h>
#include <stdint.h>

#define BB   2
#define SS   2048
#define DMODEL 1024
#define HQ   16
#define HKV  4
#define DK   64
#define KVD  256   // HKV*DK

// ---------------- scratch (no allocations allowed) ----------------
__device__ float g_Q[BB*SS*DMODEL];
__device__ float g_K[BB*SS*KVD];
__device__ float g_V[BB*SS*KVD];
__device__ float g_cos[SS*(DK/2)];
__device__ float g_sin[SS*(DK/2)];
// tf32 pre-converted operands
__device__ uint32_t g_xt[BB*SS*DMODEL];
__device__ uint32_t g_wqt[DMODEL*DMODEL];
__device__ uint32_t g_wkt[KVD*DMODEL];
__device__ uint32_t g_wvt[KVD*DMODEL];
__device__ uint32_t g_wot[DMODEL*DMODEL];
__device__ uint32_t g_attnt[BB*SS*DMODEL];   // attention output, tf32 words
// tf32 pre-converted, tile-interleaved K/V: 256 tiles x 4096 words each
__device__ uint32_t g_Kt[256*4096];
__device__ uint32_t g_Vt[256*4096];

// ---------------- helpers ----------------
__device__ __forceinline__ uint32_t f2tf(float x) {
    uint32_t r; asm("cvt.rna.tf32.f32 %0, %1;" : "=r"(r) : "f"(x)); return r;
}

__device__ __forceinline__ void mma_tf32(float* c, const uint32_t* a, const uint32_t* b) {
    asm volatile(
        "mma.sync.aligned.m16n8k8.row.col.f32.tf32.tf32.f32 "
        "{%0,%1,%2,%3}, {%4,%5,%6,%7}, {%8,%9}, {%0,%1,%2,%3};\n"
        : "+f"(c[0]), "+f"(c[1]), "+f"(c[2]), "+f"(c[3])
        : "r"(a[0]), "r"(a[1]), "r"(a[2]), "r"(a[3]), "r"(b[0]), "r"(b[1]));
}

__device__ __forceinline__ uint32_t smem_u32(const void* p) {
    uint32_t a;
    asm("{ .reg .u64 t; cvta.to.shared.u64 t, %1; cvt.u32.u64 %0, t; }" : "=r"(a) : "l"(p));
    return a;
}

__device__ __forceinline__ void cp16(uint32_t saddr, const void* g) {
    asm volatile("cp.async.cg.shared.global [%0], [%1], 16;" :: "r"(saddr), "l"(g));
}
#define CP_COMMIT() asm volatile("cp.async.commit_group;" ::: "memory")
#define CP_WAIT0()  asm volatile("cp.async.wait_group 0;" ::: "memory")

// ---------------- RoPE table ----------------
// theta_j = 1/(10000^(2j)/64); j>=5 -> inf -> theta=0 (fp32 overflow, matches ref)
__global__ void freq_rope_kernel(float* __restrict__ cosT, float* __restrict__ sinT) {
    int idx = blockIdx.x * blockDim.x + threadIdx.x;
    if (idx >= SS * (DK/2)) return;
    int s = idx / (DK/2);
    int j = idx % (DK/2);
    float p = powf(10000.0f, 2.0f * (float)j);
    float theta = 1.0f / (p / (float)DK);
    float ang = (float)s * theta;
    double a = (double)ang;
    cosT[idx] = (float)cos(a);
    sinT[idx] = (float)sin(a);
}

// Reference quirk: out1 = x1*c - x2*s ; out2 = x2*s + x1*c  (R4-identical)
__global__ void rope_kernel() {
    int idx = blockIdx.x * blockDim.x + threadIdx.x;
    const int nQ = BB*SS*HQ*(DK/2);
    const int nK = BB*SS*HKV*(DK/2);
    if (idx < nQ) {
        int pr = idx & 31;
        int t  = idx >> 5;
        int h  = t % HQ;  t /= HQ;
        int s  = t % SS;
        int b  = t / SS;
        float* p = g_Q + ((size_t)(b*SS + s))*DMODEL + h*DK + pr*2;
        float c  = g_cos[s*(DK/2) + pr];
        float sn = g_sin[s*(DK/2) + pr];
        float x1 = p[0], x2 = p[1];
        p[0] = x1*c - x2*sn;
        p[1] = x2*sn + x1*c;
    } else if (idx < nQ + nK) {
        int j  = idx - nQ;
        int pr = j & 31;
        int t  = j >> 5;
        int h  = t % HKV; t /= HKV;
        int s  = t % SS;
        int b  = t / SS;
        float* p = g_K + ((size_t)(b*SS + s))*KVD + h*DK + pr*2;
        float c  = g_cos[s*(DK/2) + pr];
        float sn = g_sin[s*(DK/2) + pr];
        float x1 = p[0], x2 = p[1];
        p[0] = x1*c - x2*sn;
        p[1] = x2*sn + x1*c;
    }
}

// ---------------- prep: x + weights -> tf32 gmem -----------------------------
#define NXT (BB*SS*DMODEL)          // 4194304
#define NWQ (DMODEL*DMODEL)         // 1048576
#define NWK (KVD*DMODEL)            // 262144
#define PREP_W_TOTAL (NXT + NWQ + 2*NWK + NWQ)   // 6815744

__global__ void prep_w(const float* __restrict__ x,
                       const float* __restrict__ wq, const float* __restrict__ wk,
                       const float* __restrict__ wv, const float* __restrict__ wo) {
    int idx = blockIdx.x * blockDim.x + threadIdx.x;
    if (idx < NXT) { g_xt[idx] = f2tf(x[idx]); return; }
    idx -= NXT;
    if (idx < NWQ) { g_wqt[idx] = f2tf(wq[idx]); return; }
    idx -= NWQ;
    if (idx < NWK) { g_wkt[idx] = f2tf(wk[idx]); return; }
    idx -= NWK;
    if (idx < NWK) { g_wvt[idx] = f2tf(wv[idx]); return; }
    idx -= NWK;
    g_wot[idx] = f2tf(wo[idx]);
}

// ---------------- prep: K/V -> tf32, tile-interleaved gmem -------------------
// K tile (dense 64 words/row): w = (kk>>1)*16 + q*4 + (kk&1)*2 + h
//   <-> K[row][kk*8 + q + 4h]   (one LDS.128 = frags for kk and kk+1)
// V tile (dense 128 words/slot): w = (n>>1)*32 + r1*4 + (n&1)*2 + h
//   <-> V[key][n*8 + r1] with PERMUTED key = (slot>>2)*8 + 2*(slot&3) + h,
//   so the PV A-fragment is the thread's own P registers (no transpose).
__global__ void prep_kv() {
    int idx = blockIdx.x * blockDim.x + threadIdx.x;
    const int NK = 256*4096;
    if (idx < NK) {
        int w = idx & 63, row = (idx >> 6) & 63, tile = (idx >> 12) & 31;
        int kvh = (idx >> 17) & 3, b = idx >> 19;
        int kk2 = w >> 4, rem = w & 15;
        int q = rem >> 2, t = rem & 3;
        int kk = kk2*2 + (t >> 1), h = t & 1;
        int col = kk*8 + q + 4*h;
        float v = g_K[((size_t)(b*SS + tile*64 + row))*KVD + kvh*DK + col];
        g_Kt[idx] = f2tf(v);
    } else {
        int j = idx - NK;
        int w = j & 127, slot = (j >> 7) & 31, tile = (j >> 12) & 31;
        int kvh = (j >> 17) & 3, b = j >> 19;
        int n2 = w >> 5, rem = w & 31;
        int r1v = rem >> 2, t = rem & 3;
        int n = n2*2 + (t >> 1), h = t & 1;
        int d = n*8 + r1v;
        int k = (slot >> 2)*8 + 2*(slot & 3) + h;   // permuted key mapping
        float v = g_V[((size_t)(b*SS + tile*64 + k))*KVD + kvh*DK + d];
        g_Vt[j] = f2tf(v);
    }
}

// ---------------- tf32 GEMM: cp.async staging of pre-converted operands ------
// Same smem layout / fragment loads / MMA order as before -> bit-identical.
#define GST 20

__device__ __forceinline__ void gemm_body(
        const uint32_t* __restrict__ A, const uint32_t* __restrict__ W,
        const float* __restrict__ bias, float* __restrict__ C,
        int N, int Kd, int rowbase, int colbase) {
    __shared__ uint32_t As[2][128*GST];
    __shared__ uint32_t Bs[2][128*GST];
    uint32_t smbA = smem_u32(As);
    uint32_t smbB = smem_u32(Bs);
    int tid = threadIdx.x;
    int lane = tid & 31, warp = tid >> 5;
    int wm = warp >> 2, wn = warp & 3;

    float acc[4][4][4];
#pragma unroll
    for (int a = 0; a < 4; a++)
#pragma unroll
        for (int b = 0; b < 4; b++)
#pragma unroll
            for (int c = 0; c < 4; c++) acc[a][b][c] = 0.0f;

    int lr = tid >> 2;
    int kc = (tid & 3) * 4;

    const uint32_t* Arow0 = &A[(size_t)(rowbase + lr)*Kd + kc];
    const uint32_t* Arow1 = &A[(size_t)(rowbase + lr + 64)*Kd + kc];
    const uint32_t* Wrow0 = &W[(size_t)(colbase + lr)*Kd + kc];
    const uint32_t* Wrow1 = &W[(size_t)(colbase + lr + 64)*Kd + kc];
    uint32_t dA0 = smbA + (lr*GST + kc)*4;
    uint32_t dA1 = smbA + ((lr+64)*GST + kc)*4;
    uint32_t dB0 = smbB + (lr*GST + kc)*4;
    uint32_t dB1 = smbB + ((lr+64)*GST + kc)*4;
    const uint32_t SOFF = 128*GST*4;

    // prefetch k-tile 0
    cp16(dA0, Arow0); cp16(dA1, Arow1);
    cp16(dB0, Wrow0); cp16(dB1, Wrow1);
    CP_COMMIT();
    CP_WAIT0();
    __syncthreads();

    int nk = Kd / 16;
    for (int t = 0; t < nk; t++) {
        int s = t & 1;
        if (t + 1 < nk) {
            int kb = (t+1)*16;
            uint32_t so = (s^1) ? SOFF : 0;
            cp16(dA0 + so, Arow0 + kb); cp16(dA1 + so, Arow1 + kb);
            cp16(dB0 + so, Wrow0 + kb); cp16(dB1 + so, Wrow1 + kb);
            CP_COMMIT();
        }
#pragma unroll
        for (int ks = 0; ks < 2; ks++) {
            int k0 = ks * 8;
            uint32_t af[4][4], bf[4][2];
#pragma unroll
            for (int mi = 0; mi < 4; mi++) {
                int row = wm*64 + mi*16 + (lane >> 2);
                const uint32_t* p = &As[s][row*GST + k0 + (lane & 3)];
                af[mi][0] = p[0];
                af[mi][1] = p[8*GST];
                af[mi][2] = p[4];
                af[mi][3] = p[8*GST + 4];
            }
#pragma unroll
            for (int ni = 0; ni < 4; ni++) {
                int col = wn*32 + ni*8 + (lane >> 2);
                const uint32_t* p = &Bs[s][col*GST + k0 + (lane & 3)];
                bf[ni][0] = p[0];
                bf[ni][1] = p[4];
            }
#pragma unroll
            for (int mi = 0; mi < 4; mi++)
#pragma unroll
                for (int ni = 0; ni < 4; ni++)
                    mma_tf32(acc[mi][ni], af[mi], bf[ni]);
        }
        if (t + 1 < nk) CP_WAIT0();
        __syncthreads();
    }

#pragma unroll
    for (int mi = 0; mi < 4; mi++) {
        int row = rowbase + wm*64 + mi*16 + (lane >> 2);
#pragma unroll
        for (int ni = 0; ni < 4; ni++) {
            int col = colbase + wn*32 + ni*8 + 2*(lane & 3);
            float c0 = bias[col], c1 = bias[col+1];
            float2 v0 = {acc[mi][ni][0] + c0, acc[mi][ni][1] + c1};
            *(float2*)&C[(size_t)row*N + col] = v0;
            float2 v1 = {acc[mi][ni][2] + c0, acc[mi][ni][3] + c1};
            *(float2*)&C[(size_t)(row+8)*N + col] = v1;
        }
    }
}

// Fused Q+K+V projection (384 CTAs).
__global__ void __launch_bounds__(256) gemm_qkv(
        const float* __restrict__ bq, const float* __restrict__ bk,
        const float* __restrict__ bv) {
    int id = blockIdx.x;
    const uint32_t* W; const float* bias; float* C;
    int N, rowbase, colbase;
    if (id < 256) {
        W = g_wqt; bias = bq; C = g_Q; N = DMODEL;
        rowbase = (id >> 3) * 128; colbase = (id & 7) * 128;
    } else if (id < 320) {
        int i = id - 256;
        W = g_wkt; bias = bk; C = g_K; N = KVD;
        rowbase = (i >> 1) * 128; colbase = (i & 1) * 128;
    } else {
        int i = id - 320;
        W = g_wvt; bias = bv; C = g_V; N = KVD;
        rowbase = (i >> 1) * 128; colbase = (i & 1) * 128;
    }
    gemm_body(g_xt, W, bias, C, N, DMODEL, rowbase, colbase);
}

// Output projection (A = attention output, already tf32).
__global__ void __launch_bounds__(256) gemm_o(
        const float* __restrict__ bias, float* __restrict__ C) {
    gemm_body(g_attnt, g_wot, bias, C, DMODEL, DMODEL, blockIdx.y*128, blockIdx.x*128);
}

// ---------------- flash attention: permuted-V, transpose-free PV -------------
// Unchanged from R13 except the epilogue writes tf32 words to g_attnt
// (same f2tf values gemm_o previously computed -> bit-identical).
#define KP_ST 80
#define VP_ST 136
#define STAGE_W (64*KP_ST + 32*VP_ST)      // 9472 words
#define ATT_SMEM (2*STAGE_W*4)             // 75776 bytes

__device__ __forceinline__ void issue_tile(uint32_t dstK, uint32_t dstV,
                                           const uint32_t* Kt, const uint32_t* Vt,
                                           int kt, int tid) {
    const char* srcK = (const char*)(Kt + (size_t)kt*4096);
    const char* srcV = (const char*)(Vt + (size_t)kt*4096);
#pragma unroll
    for (int i = 0; i < 4; i++) {
        int c = tid + 256*i;
        cp16(dstK + (c >> 4)*(KP_ST*4) + (c & 15)*16, srcK + c*16);
        cp16(dstV + (c >> 5)*(VP_ST*4) + (c & 31)*16, srcV + c*16);
    }
    CP_COMMIT();
}

__global__ void __launch_bounds__(256, 2) attn_tf32() {
    extern __shared__ uint32_t smA[];
    uint32_t smb = smem_u32(smA);

    int tid = threadIdx.x, lane = tid & 31, warp = tid >> 5;
    int g = warp >> 2, sub = warp & 3;
    int qt = (int)gridDim.x - 1 - (int)blockIdx.x;
    int y = blockIdx.y;
    int b = y >> 3, kvh = (y >> 1) & 3, hg = y & 1;
    int h = kvh*4 + hg*2 + g;

    const float* Qb = g_Q + (size_t)b*SS*DMODEL + h*DK;
    const uint32_t* Ktb = g_Kt + (size_t)((b*4 + kvh)*32)*4096;
    const uint32_t* Vtb = g_Vt + (size_t)((b*4 + kvh)*32)*4096;
    int q0 = qt * 64;
    int r1 = lane >> 2;
    int q  = lane & 3;
    int qrow = 16*sub + r1;

    // Q fragments, pre-scaled by 1/sqrt(64)
    uint32_t qf[8][4];
#pragma unroll
    for (int kk = 0; kk < 8; kk++) {
        int d = kk*8 + q;
        const float* p = &Qb[(size_t)(q0 + qrow)*DMODEL + d];
        qf[kk][0] = f2tf(p[0] * 0.125f);
        qf[kk][1] = f2tf(p[(size_t)8*DMODEL] * 0.125f);
        qf[kk][2] = f2tf(p[4] * 0.125f);
        qf[kk][3] = f2tf(p[(size_t)8*DMODEL + 4] * 0.125f);
    }

    float m1 = -1e30f, m2 = -1e30f, l1 = 0.0f, l2 = 0.0f;
    float of[8][4];
#pragma unroll
    for (int n = 0; n < 8; n++)
#pragma unroll
        for (int j = 0; j < 4; j++) of[n][j] = 0.0f;

    // prefetch tile 0 directly into stage 0
    issue_tile(smb, smb + 64*KP_ST*4, Ktb, Vtb, 0, tid);
    CP_WAIT0();
    __syncthreads();

    for (int kt = 0; kt <= qt; kt++) {
        int s = kt & 1;
        const uint32_t* Kp = smA + s*STAGE_W;
        const uint32_t* Vp = Kp + 64*KP_ST;

        // issue cp.async for next tile into the other stage
        if (kt < qt) {
            uint32_t dst = smb + (s^1)*STAGE_W*4;
            issue_tile(dst, dst + 64*KP_ST*4, Ktb, Vtb, kt+1, tid);
        }

        // S = (Q/8) K^T   (LDS.128 = 2 B-frags; per-acc kk order 0..7)
        float sf[8][4];
#pragma unroll
        for (int n = 0; n < 8; n++)
#pragma unroll
            for (int j = 0; j < 4; j++) sf[n][j] = 0.0f;
#pragma unroll
        for (int kk2 = 0; kk2 < 4; kk2++) {
#pragma unroll
            for (int n = 0; n < 8; n++) {
                int key = n*8 + r1;
                uint4 b4 = *(const uint4*)&Kp[key*KP_ST + kk2*16 + q*4];
                uint32_t bf0[2] = {b4.x, b4.y};
                mma_tf32(sf[n], qf[2*kk2], bf0);
                uint32_t bf1[2] = {b4.z, b4.w};
                mma_tf32(sf[n], qf[2*kk2+1], bf1);
            }
        }

        // causal mask on diagonal tile
        if (kt == qt) {
#pragma unroll
            for (int n = 0; n < 8; n++) {
                int col = n*8 + 2*q;
                if (col     > qrow)     sf[n][0] = -1e30f;
                if (col + 1 > qrow)     sf[n][1] = -1e30f;
                if (col     > qrow + 8) sf[n][2] = -1e30f;
                if (col + 1 > qrow + 8) sf[n][3] = -1e30f;
            }
        }

        // online softmax
        float mx1 = -1e30f, mx2 = -1e30f;
#pragma unroll
        for (int n = 0; n < 8; n++) {
            mx1 = fmaxf(mx1, fmaxf(sf[n][0], sf[n][1]));
            mx2 = fmaxf(mx2, fmaxf(sf[n][2], sf[n][3]));
        }
        mx1 = fmaxf(mx1, __shfl_xor_sync(0xffffffffu, mx1, 1));
        mx1 = fmaxf(mx1, __shfl_xor_sync(0xffffffffu, mx1, 2));
        mx2 = fmaxf(mx2, __shfl_xor_sync(0xffffffffu, mx2, 1));
        mx2 = fmaxf(mx2, __shfl_xor_sync(0xffffffffu, mx2, 2));
        float mn1 = fmaxf(m1, mx1), mn2 = fmaxf(m2, mx2);
        float c1 = __expf(m1 - mn1), c2 = __expf(m2 - mn2);
        float s1 = 0.0f, s2 = 0.0f;
#pragma unroll
        for (int n = 0; n < 8; n++) {
            sf[n][0] = __expf(sf[n][0] - mn1);
            sf[n][1] = __expf(sf[n][1] - mn1);
            sf[n][2] = __expf(sf[n][2] - mn2);
            sf[n][3] = __expf(sf[n][3] - mn2);
            s1 += sf[n][0] + sf[n][1];
            s2 += sf[n][2] + sf[n][3];
        }
        s1 += __shfl_xor_sync(0xffffffffu, s1, 1);
        s1 += __shfl_xor_sync(0xffffffffu, s1, 2);
        s2 += __shfl_xor_sync(0xffffffffu, s2, 1);
        s2 += __shfl_xor_sync(0xffffffffu, s2, 2);
        l1 = l1*c1 + s1;  l2 = l2*c2 + s2;
        m1 = mn1;         m2 = mn2;
#pragma unroll
        for (int n = 0; n < 8; n++) {
            of[n][0] *= c1; of[n][1] *= c1;
            of[n][2] *= c2; of[n][3] *= c2;
        }

        // O += P V ; A-frag = OWN registers (V key-permuted), no transpose
#pragma unroll
        for (int kk = 0; kk < 8; kk++) {
            uint32_t pa[4];
            pa[0] = f2tf(sf[kk][0]);   // P[qrow  ][key 2q  ]
            pa[1] = f2tf(sf[kk][2]);   // P[qrow+8][key 2q  ]
            pa[2] = f2tf(sf[kk][1]);   // P[qrow  ][key 2q+1]
            pa[3] = f2tf(sf[kk][3]);   // P[qrow+8][key 2q+1]
            int slot = kk*4 + q;
#pragma unroll
            for (int n2 = 0; n2 < 4; n2++) {
                uint4 v4 = *(const uint4*)&Vp[slot*VP_ST + n2*32 + r1*4];
                uint32_t vb0[2] = {v4.x, v4.y};
                mma_tf32(of[2*n2], pa, vb0);
                uint32_t vb1[2] = {v4.z, v4.w};
                mma_tf32(of[2*n2+1], pa, vb1);
            }
        }

        // next stage: own copies done + barrier makes all threads' copies visible
        if (kt < qt) CP_WAIT0();
        __syncthreads();
    }

    float inv1 = 1.0f / l1, inv2 = 1.0f / l2;
    uint32_t* Ot = g_attnt + (size_t)b*SS*DMODEL + h*DK;
#pragma unroll
    for (int n = 0; n < 8; n++) {
        int col = n*8 + 2*q;
        uint2 w0 = {f2tf(of[n][0]*inv1), f2tf(of[n][1]*inv1)};
        *(uint2*)&Ot[(size_t)(q0 + qrow)*DMODEL + col] = w0;
        uint2 w1 = {f2tf(of[n][2]*inv2), f2tf(of[n][3]*inv2)};
        *(uint2*)&Ot[(size_t)(q0 + qrow + 8)*DMODEL + col] = w1;
    }
}

// ---------------- launch ----------------
extern "C" void kernel_launch(void* const* d_in, const int* in_sizes, int n_in,
                              void* d_out, int out_size) {
    const float* x  = (const float*)d_in[0];
    const float* wq = (const float*)d_in[1];
    const float* bq = (const float*)d_in[2];
    const float* wk = (const float*)d_in[3];
    const float* bk = (const float*)d_in[4];
    const float* wv = (const float*)d_in[5];
    const float* bv = (const float*)d_in[6];
    const float* wo = (const float*)d_in[7];
    const float* bo = (const float*)d_in[8];
    float* out = (float*)d_out;

    float *cT, *sT;
    cudaGetSymbolAddress((void**)&cT, g_cos);
    cudaGetSymbolAddress((void**)&sT, g_sin);

    static int cfg_done = 0;
    if (!cfg_done) {
        cudaFuncSetAttribute(attn_tf32, cudaFuncAttributeMaxDynamicSharedMemorySize, ATT_SMEM);
        cfg_done = 1;
    }

    // RoPE tables + operand pre-conversion (independent)
    freq_rope_kernel<<<(SS*(DK/2) + 255)/256, 256>>>(cT, sT);
    prep_w<<<(PREP_W_TOTAL + 255)/256, 256>>>(x, wq, wk, wv, wo);

    // fused Q+K+V projections (one launch)
    gemm_qkv<<<384, 256>>>(bq, bk, bv);

    // RoPE applied in-place on Q and K
    {
        int total = BB*SS*HQ*(DK/2) + BB*SS*HKV*(DK/2);
        rope_kernel<<<(total + 255)/256, 256>>>();
    }

    // pre-convert K/V to tf32 tile-interleaved layouts
    prep_kv<<<(2*256*4096)/256, 256>>>();

    // attention (2 heads per CTA share K/V), writes tf32 g_attnt
    attn_tf32<<<dim3(SS/64, BB*HKV*2), 256, ATT_SMEM>>>();

    // output projection
    gemm_o<<<dim3(DMODEL/128, BB*SS/128), 256>>>(bo, out);
}

// round 16
// speedup vs baseline: 1.0042x; 1.0042x over previous
#include <cuda_runtime.h>
#include <math.h>
#include <stdint.h>

#define BB   2
#define SS   2048
#define DMODEL 1024
#define HQ   16
#define HKV  4
#define DK   64
#define KVD  256   // HKV*DK

// ---------------- scratch (no allocations allowed) ----------------
__device__ float g_Q[BB*SS*DMODEL];
__device__ float g_K[BB*SS*KVD];
__device__ float g_V[BB*SS*KVD];
__device__ float g_cos[SS*(DK/2)];
__device__ float g_sin[SS*(DK/2)];
// tf32 pre-converted operands
__device__ uint32_t g_xt[BB*SS*DMODEL];
__device__ uint32_t g_wqt[DMODEL*DMODEL];
__device__ uint32_t g_wkt[KVD*DMODEL];
__device__ uint32_t g_wvt[KVD*DMODEL];
__device__ uint32_t g_wot[DMODEL*DMODEL];
__device__ uint32_t g_attnt[BB*SS*DMODEL];   // attention output, tf32 words
// tf32 pre-converted, tile-interleaved K/V: 256 tiles x 4096 words each
__device__ uint32_t g_Kt[256*4096];
__device__ uint32_t g_Vt[256*4096];

// ---------------- helpers ----------------
__device__ __forceinline__ uint32_t f2tf(float x) {
    uint32_t r; asm("cvt.rna.tf32.f32 %0, %1;" : "=r"(r) : "f"(x)); return r;
}

__device__ __forceinline__ void mma_tf32(float* c, const uint32_t* a, const uint32_t* b) {
    asm volatile(
        "mma.sync.aligned.m16n8k8.row.col.f32.tf32.tf32.f32 "
        "{%0,%1,%2,%3}, {%4,%5,%6,%7}, {%8,%9}, {%0,%1,%2,%3};\n"
        : "+f"(c[0]), "+f"(c[1]), "+f"(c[2]), "+f"(c[3])
        : "r"(a[0]), "r"(a[1]), "r"(a[2]), "r"(a[3]), "r"(b[0]), "r"(b[1]));
}

__device__ __forceinline__ uint32_t smem_u32(const void* p) {
    uint32_t a;
    asm("{ .reg .u64 t; cvta.to.shared.u64 t, %1; cvt.u32.u64 %0, t; }" : "=r"(a) : "l"(p));
    return a;
}

__device__ __forceinline__ void cp16(uint32_t saddr, const void* g) {
    asm volatile("cp.async.cg.shared.global [%0], [%1], 16;" :: "r"(saddr), "l"(g));
}
#define CP_COMMIT() asm volatile("cp.async.commit_group;" ::: "memory")
#define CP_WAIT0()  asm volatile("cp.async.wait_group 0;" ::: "memory")

// Rope of one element at within-head column d of row base rp, seq position spos.
// Identical formula/order to the old rope_kernel -> bit-identical values.
__device__ __forceinline__ float rope_elem(const float* rp, int d, int spos) {
    int pr = d >> 1;
    float c  = g_cos[spos*32 + pr];
    float sn = g_sin[spos*32 + pr];
    float x1 = rp[d & ~1], x2 = rp[d | 1];
    return (d & 1) ? (x2*sn + x1*c) : (x1*c - x2*sn);
}

// ---------------- RoPE table ----------------
// theta_j = 1/(10000^(2j)/64); j>=5 -> inf -> theta=0 (fp32 overflow, matches ref)
__global__ void freq_rope_kernel(float* __restrict__ cosT, float* __restrict__ sinT) {
    int idx = blockIdx.x * blockDim.x + threadIdx.x;
    if (idx >= SS * (DK/2)) return;
    int s = idx / (DK/2);
    int j = idx % (DK/2);
    float p = powf(10000.0f, 2.0f * (float)j);
    float theta = 1.0f / (p / (float)DK);
    float ang = (float)s * theta;
    double a = (double)ang;
    cosT[idx] = (float)cos(a);
    sinT[idx] = (float)sin(a);
}

// ---------------- prep: x + weights -> tf32 gmem -----------------------------
#define NXT (BB*SS*DMODEL)          // 4194304
#define NWQ (DMODEL*DMODEL)         // 1048576
#define NWK (KVD*DMODEL)            // 262144
#define PREP_W_TOTAL (NXT + NWQ + 2*NWK + NWQ)   // 6815744

__global__ void prep_w(const float* __restrict__ x,
                       const float* __restrict__ wq, const float* __restrict__ wk,
                       const float* __restrict__ wv, const float* __restrict__ wo) {
    int idx = blockIdx.x * blockDim.x + threadIdx.x;
    if (idx < NXT) { g_xt[idx] = f2tf(x[idx]); return; }
    idx -= NXT;
    if (idx < NWQ) { g_wqt[idx] = f2tf(wq[idx]); return; }
    idx -= NWQ;
    if (idx < NWK) { g_wkt[idx] = f2tf(wk[idx]); return; }
    idx -= NWK;
    if (idx < NWK) { g_wvt[idx] = f2tf(wv[idx]); return; }
    idx -= NWK;
    g_wot[idx] = f2tf(wo[idx]);
}

// ---------------- prep: K/V -> tf32, tile-interleaved gmem, K-rope fused -----
// K tile (dense 64 words/row): w = (kk>>1)*16 + q*4 + (kk&1)*2 + h
//   <-> rope(K)[row][kk*8 + q + 4h]
// V tile (dense 128 words/slot): w = (n>>1)*32 + r1*4 + (n&1)*2 + h
//   <-> V[key][n*8 + r1] with PERMUTED key = (slot>>2)*8 + 2*(slot&3) + h.
__global__ void prep_kv() {
    int idx = blockIdx.x * blockDim.x + threadIdx.x;
    const int NK = 256*4096;
    if (idx < NK) {
        int w = idx & 63, row = (idx >> 6) & 63, tile = (idx >> 12) & 31;
        int kvh = (idx >> 17) & 3, b = idx >> 19;
        int kk2 = w >> 4, rem = w & 15;
        int q = rem >> 2, t = rem & 3;
        int kk = kk2*2 + (t >> 1), h = t & 1;
        int col = kk*8 + q + 4*h;
        int spos = tile*64 + row;
        const float* rp = &g_K[((size_t)(b*SS + spos))*KVD + kvh*DK];
        g_Kt[idx] = f2tf(rope_elem(rp, col, spos));
    } else {
        int j = idx - NK;
        int w = j & 127, slot = (j >> 7) & 31, tile = (j >> 12) & 31;
        int kvh = (j >> 17) & 3, b = j >> 19;
        int n2 = w >> 5, rem = w & 31;
        int r1v = rem >> 2, t = rem & 3;
        int n = n2*2 + (t >> 1), h = t & 1;
        int d = n*8 + r1v;
        int k = (slot >> 2)*8 + 2*(slot & 3) + h;   // permuted key mapping
        float v = g_V[((size_t)(b*SS + tile*64 + k))*KVD + kvh*DK + d];
        g_Vt[j] = f2tf(v);
    }
}

// ---------------- tf32 GEMM: cp.async staging of pre-converted operands ------
#define GST 20

__device__ __forceinline__ void gemm_body(
        const uint32_t* __restrict__ A, const uint32_t* __restrict__ W,
        const float* __restrict__ bias, float* __restrict__ C,
        int N, int Kd, int rowbase, int colbase) {
    __shared__ uint32_t As[2][128*GST];
    __shared__ uint32_t Bs[2][128*GST];
    uint32_t smbA = smem_u32(As);
    uint32_t smbB = smem_u32(Bs);
    int tid = threadIdx.x;
    int lane = tid & 31, warp = tid >> 5;
    int wm = warp >> 2, wn = warp & 3;

    float acc[4][4][4];
#pragma unroll
    for (int a = 0; a < 4; a++)
#pragma unroll
        for (int b = 0; b < 4; b++)
#pragma unroll
            for (int c = 0; c < 4; c++) acc[a][b][c] = 0.0f;

    int lr = tid >> 2;
    int kc = (tid & 3) * 4;

    const uint32_t* Arow0 = &A[(size_t)(rowbase + lr)*Kd + kc];
    const uint32_t* Arow1 = &A[(size_t)(rowbase + lr + 64)*Kd + kc];
    const uint32_t* Wrow0 = &W[(size_t)(colbase + lr)*Kd + kc];
    const uint32_t* Wrow1 = &W[(size_t)(colbase + lr + 64)*Kd + kc];
    uint32_t dA0 = smbA + (lr*GST + kc)*4;
    uint32_t dA1 = smbA + ((lr+64)*GST + kc)*4;
    uint32_t dB0 = smbB + (lr*GST + kc)*4;
    uint32_t dB1 = smbB + ((lr+64)*GST + kc)*4;
    const uint32_t SOFF = 128*GST*4;

    // prefetch k-tile 0
    cp16(dA0, Arow0); cp16(dA1, Arow1);
    cp16(dB0, Wrow0); cp16(dB1, Wrow1);
    CP_COMMIT();
    CP_WAIT0();
    __syncthreads();

    int nk = Kd / 16;
    for (int t = 0; t < nk; t++) {
        int s = t & 1;
        if (t + 1 < nk) {
            int kb = (t+1)*16;
            uint32_t so = (s^1) ? SOFF : 0;
            cp16(dA0 + so, Arow0 + kb); cp16(dA1 + so, Arow1 + kb);
            cp16(dB0 + so, Wrow0 + kb); cp16(dB1 + so, Wrow1 + kb);
            CP_COMMIT();
        }
#pragma unroll
        for (int ks = 0; ks < 2; ks++) {
            int k0 = ks * 8;
            uint32_t af[4][4], bf[4][2];
#pragma unroll
            for (int mi = 0; mi < 4; mi++) {
                int row = wm*64 + mi*16 + (lane >> 2);
                const uint32_t* p = &As[s][row*GST + k0 + (lane & 3)];
                af[mi][0] = p[0];
                af[mi][1] = p[8*GST];
                af[mi][2] = p[4];
                af[mi][3] = p[8*GST + 4];
            }
#pragma unroll
            for (int ni = 0; ni < 4; ni++) {
                int col = wn*32 + ni*8 + (lane >> 2);
                const uint32_t* p = &Bs[s][col*GST + k0 + (lane & 3)];
                bf[ni][0] = p[0];
                bf[ni][1] = p[4];
            }
#pragma unroll
            for (int mi = 0; mi < 4; mi++)
#pragma unroll
                for (int ni = 0; ni < 4; ni++)
                    mma_tf32(acc[mi][ni], af[mi], bf[ni]);
        }
        if (t + 1 < nk) CP_WAIT0();
        __syncthreads();
    }

#pragma unroll
    for (int mi = 0; mi < 4; mi++) {
        int row = rowbase + wm*64 + mi*16 + (lane >> 2);
#pragma unroll
        for (int ni = 0; ni < 4; ni++) {
            int col = colbase + wn*32 + ni*8 + 2*(lane & 3);
            float c0 = bias[col], c1 = bias[col+1];
            float2 v0 = {acc[mi][ni][0] + c0, acc[mi][ni][1] + c1};
            *(float2*)&C[(size_t)row*N + col] = v0;
            float2 v1 = {acc[mi][ni][2] + c0, acc[mi][ni][3] + c1};
            *(float2*)&C[(size_t)(row+8)*N + col] = v1;
        }
    }
}

// Fused Q+K+V projection (384 CTAs). Writes RAW (un-roped) Q/K; rope is
// applied by the consumers (attn prologue / prep_kv).
__global__ void __launch_bounds__(256) gemm_qkv(
        const float* __restrict__ bq, const float* __restrict__ bk,
        const float* __restrict__ bv) {
    int id = blockIdx.x;
    const uint32_t* W; const float* bias; float* C;
    int N, rowbase, colbase;
    if (id < 256) {
        W = g_wqt; bias = bq; C = g_Q; N = DMODEL;
        rowbase = (id >> 3) * 128; colbase = (id & 7) * 128;
    } else if (id < 320) {
        int i = id - 256;
        W = g_wkt; bias = bk; C = g_K; N = KVD;
        rowbase = (i >> 1) * 128; colbase = (i & 1) * 128;
    } else {
        int i = id - 320;
        W = g_wvt; bias = bv; C = g_V; N = KVD;
        rowbase = (i >> 1) * 128; colbase = (i & 1) * 128;
    }
    gemm_body(g_xt, W, bias, C, N, DMODEL, rowbase, colbase);
}

// Output projection (A = attention output, already tf32).
__global__ void __launch_bounds__(256) gemm_o(
        const float* __restrict__ bias, float* __restrict__ C) {
    gemm_body(g_attnt, g_wot, bias, C, DMODEL, DMODEL, blockIdx.y*128, blockIdx.x*128);
}

// ---------------- flash attention: permuted-V, transpose-free PV -------------
// Q-rope fused into the fragment prologue (same formula -> bit-identical qf).
#define KP_ST 80
#define VP_ST 136
#define STAGE_W (64*KP_ST + 32*VP_ST)      // 9472 words
#define ATT_SMEM (2*STAGE_W*4)             // 75776 bytes

__device__ __forceinline__ void issue_tile(uint32_t dstK, uint32_t dstV,
                                           const uint32_t* Kt, const uint32_t* Vt,
                                           int kt, int tid) {
    const char* srcK = (const char*)(Kt + (size_t)kt*4096);
    const char* srcV = (const char*)(Vt + (size_t)kt*4096);
#pragma unroll
    for (int i = 0; i < 4; i++) {
        int c = tid + 256*i;
        cp16(dstK + (c >> 4)*(KP_ST*4) + (c & 15)*16, srcK + c*16);
        cp16(dstV + (c >> 5)*(VP_ST*4) + (c & 31)*16, srcV + c*16);
    }
    CP_COMMIT();
}

__global__ void __launch_bounds__(256, 2) attn_tf32() {
    extern __shared__ uint32_t smA[];
    uint32_t smb = smem_u32(smA);

    int tid = threadIdx.x, lane = tid & 31, warp = tid >> 5;
    int g = warp >> 2, sub = warp & 3;
    int qt = (int)gridDim.x - 1 - (int)blockIdx.x;
    int y = blockIdx.y;
    int b = y >> 3, kvh = (y >> 1) & 3, hg = y & 1;
    int h = kvh*4 + hg*2 + g;

    const float* Qb = g_Q + (size_t)b*SS*DMODEL + h*DK;
    const uint32_t* Ktb = g_Kt + (size_t)((b*4 + kvh)*32)*4096;
    const uint32_t* Vtb = g_Vt + (size_t)((b*4 + kvh)*32)*4096;
    int q0 = qt * 64;
    int r1 = lane >> 2;
    int q  = lane & 3;
    int qrow = 16*sub + r1;

    // Q fragments: rope applied inline, then pre-scaled by 1/sqrt(64)
    uint32_t qf[8][4];
    {
        int s0 = q0 + qrow, s8 = s0 + 8;
        const float* rp0 = &Qb[(size_t)s0*DMODEL];
        const float* rp8 = &Qb[(size_t)s8*DMODEL];
#pragma unroll
        for (int kk = 0; kk < 8; kk++) {
            int d = kk*8 + q;
            qf[kk][0] = f2tf(rope_elem(rp0, d,     s0) * 0.125f);
            qf[kk][1] = f2tf(rope_elem(rp8, d,     s8) * 0.125f);
            qf[kk][2] = f2tf(rope_elem(rp0, d + 4, s0) * 0.125f);
            qf[kk][3] = f2tf(rope_elem(rp8, d + 4, s8) * 0.125f);
        }
    }

    float m1 = -1e30f, m2 = -1e30f, l1 = 0.0f, l2 = 0.0f;
    float of[8][4];
#pragma unroll
    for (int n = 0; n < 8; n++)
#pragma unroll
        for (int j = 0; j < 4; j++) of[n][j] = 0.0f;

    // prefetch tile 0 directly into stage 0
    issue_tile(smb, smb + 64*KP_ST*4, Ktb, Vtb, 0, tid);
    CP_WAIT0();
    __syncthreads();

    for (int kt = 0; kt <= qt; kt++) {
        int s = kt & 1;
        const uint32_t* Kp = smA + s*STAGE_W;
        const uint32_t* Vp = Kp + 64*KP_ST;

        // issue cp.async for next tile into the other stage
        if (kt < qt) {
            uint32_t dst = smb + (s^1)*STAGE_W*4;
            issue_tile(dst, dst + 64*KP_ST*4, Ktb, Vtb, kt+1, tid);
        }

        // S = (Q/8) K^T   (LDS.128 = 2 B-frags; per-acc kk order 0..7)
        float sf[8][4];
#pragma unroll
        for (int n = 0; n < 8; n++)
#pragma unroll
            for (int j = 0; j < 4; j++) sf[n][j] = 0.0f;
#pragma unroll
        for (int kk2 = 0; kk2 < 4; kk2++) {
#pragma unroll
            for (int n = 0; n < 8; n++) {
                int key = n*8 + r1;
                uint4 b4 = *(const uint4*)&Kp[key*KP_ST + kk2*16 + q*4];
                uint32_t bf0[2] = {b4.x, b4.y};
                mma_tf32(sf[n], qf[2*kk2], bf0);
                uint32_t bf1[2] = {b4.z, b4.w};
                mma_tf32(sf[n], qf[2*kk2+1], bf1);
            }
        }

        // causal mask on diagonal tile
        if (kt == qt) {
#pragma unroll
            for (int n = 0; n < 8; n++) {
                int col = n*8 + 2*q;
                if (col     > qrow)     sf[n][0] = -1e30f;
                if (col + 1 > qrow)     sf[n][1] = -1e30f;
                if (col     > qrow + 8) sf[n][2] = -1e30f;
                if (col + 1 > qrow + 8) sf[n][3] = -1e30f;
            }
        }

        // online softmax
        float mx1 = -1e30f, mx2 = -1e30f;
#pragma unroll
        for (int n = 0; n < 8; n++) {
            mx1 = fmaxf(mx1, fmaxf(sf[n][0], sf[n][1]));
            mx2 = fmaxf(mx2, fmaxf(sf[n][2], sf[n][3]));
        }
        mx1 = fmaxf(mx1, __shfl_xor_sync(0xffffffffu, mx1, 1));
        mx1 = fmaxf(mx1, __shfl_xor_sync(0xffffffffu, mx1, 2));
        mx2 = fmaxf(mx2, __shfl_xor_sync(0xffffffffu, mx2, 1));
        mx2 = fmaxf(mx2, __shfl_xor_sync(0xffffffffu, mx2, 2));
        float mn1 = fmaxf(m1, mx1), mn2 = fmaxf(m2, mx2);
        float c1 = __expf(m1 - mn1), c2 = __expf(m2 - mn2);
        float s1 = 0.0f, s2 = 0.0f;
#pragma unroll
        for (int n = 0; n < 8; n++) {
            sf[n][0] = __expf(sf[n][0] - mn1);
            sf[n][1] = __expf(sf[n][1] - mn1);
            sf[n][2] = __expf(sf[n][2] - mn2);
            sf[n][3] = __expf(sf[n][3] - mn2);
            s1 += sf[n][0] + sf[n][1];
            s2 += sf[n][2] + sf[n][3];
        }
        s1 += __shfl_xor_sync(0xffffffffu, s1, 1);
        s1 += __shfl_xor_sync(0xffffffffu, s1, 2);
        s2 += __shfl_xor_sync(0xffffffffu, s2, 1);
        s2 += __shfl_xor_sync(0xffffffffu, s2, 2);
        l1 = l1*c1 + s1;  l2 = l2*c2 + s2;
        m1 = mn1;         m2 = mn2;
#pragma unroll
        for (int n = 0; n < 8; n++) {
            of[n][0] *= c1; of[n][1] *= c1;
            of[n][2] *= c2; of[n][3] *= c2;
        }

        // O += P V ; A-frag = OWN registers (V key-permuted), no transpose
#pragma unroll
        for (int kk = 0; kk < 8; kk++) {
            uint32_t pa[4];
            pa[0] = f2tf(sf[kk][0]);   // P[qrow  ][key 2q  ]
            pa[1] = f2tf(sf[kk][2]);   // P[qrow+8][key 2q  ]
            pa[2] = f2tf(sf[kk][1]);   // P[qrow  ][key 2q+1]
            pa[3] = f2tf(sf[kk][3]);   // P[qrow+8][key 2q+1]
            int slot = kk*4 + q;
#pragma unroll
            for (int n2 = 0; n2 < 4; n2++) {
                uint4 v4 = *(const uint4*)&Vp[slot*VP_ST + n2*32 + r1*4];
                uint32_t vb0[2] = {v4.x, v4.y};
                mma_tf32(of[2*n2], pa, vb0);
                uint32_t vb1[2] = {v4.z, v4.w};
                mma_tf32(of[2*n2+1], pa, vb1);
            }
        }

        // next stage: own copies done + barrier makes all threads' copies visible
        if (kt < qt) CP_WAIT0();
        __syncthreads();
    }

    float inv1 = 1.0f / l1, inv2 = 1.0f / l2;
    uint32_t* Ot = g_attnt + (size_t)b*SS*DMODEL + h*DK;
#pragma unroll
    for (int n = 0; n < 8; n++) {
        int col = n*8 + 2*q;
        uint2 w0 = {f2tf(of[n][0]*inv1), f2tf(of[n][1]*inv1)};
        *(uint2*)&Ot[(size_t)(q0 + qrow)*DMODEL + col] = w0;
        uint2 w1 = {f2tf(of[n][2]*inv2), f2tf(of[n][3]*inv2)};
        *(uint2*)&Ot[(size_t)(q0 + qrow + 8)*DMODEL + col] = w1;
    }
}

// ---------------- launch ----------------
extern "C" void kernel_launch(void* const* d_in, const int* in_sizes, int n_in,
                              void* d_out, int out_size) {
    const float* x  = (const float*)d_in[0];
    const float* wq = (const float*)d_in[1];
    const float* bq = (const float*)d_in[2];
    const float* wk = (const float*)d_in[3];
    const float* bk = (const float*)d_in[4];
    const float* wv = (const float*)d_in[5];
    const float* bv = (const float*)d_in[6];
    const float* wo = (const float*)d_in[7];
    const float* bo = (const float*)d_in[8];
    float* out = (float*)d_out;

    float *cT, *sT;
    cudaGetSymbolAddress((void**)&cT, g_cos);
    cudaGetSymbolAddress((void**)&sT, g_sin);

    static int cfg_done = 0;
    if (!cfg_done) {
        cudaFuncSetAttribute(attn_tf32, cudaFuncAttributeMaxDynamicSharedMemorySize, ATT_SMEM);
        cfg_done = 1;
    }

    // RoPE tables + operand pre-conversion (independent)
    freq_rope_kernel<<<(SS*(DK/2) + 255)/256, 256>>>(cT, sT);
    prep_w<<<(PREP_W_TOTAL + 255)/256, 256>>>(x, wq, wk, wv, wo);

    // fused Q+K+V projections (one launch; Q/K written un-roped)
    gemm_qkv<<<384, 256>>>(bq, bk, bv);

    // pre-convert K/V to tf32 tile-interleaved layouts (K-rope fused)
    prep_kv<<<(2*256*4096)/256, 256>>>();

    // attention (Q-rope fused in prologue), writes tf32 g_attnt
    attn_tf32<<<dim3(SS/64, BB*HKV*2), 256, ATT_SMEM>>>();

    // output projection
    gemm_o<<<dim3(DMODEL/128, BB*SS/128), 256>>>(bo, out);
}

// round 17
// speedup vs baseline: 1.1125x; 1.1079x over previous
#include <cuda_runtime.h>
#include <math.h>
#include <stdint.h>

#define BB   2
#define SS   2048
#define DMODEL 1024
#define HQ   16
#define HKV  4
#define DK   64
#define KVD  256   // HKV*DK

// ---------------- scratch (no allocations allowed) ----------------
__device__ float g_Q[BB*SS*DMODEL];
__device__ float g_K[BB*SS*KVD];
__device__ float g_V[BB*SS*KVD];
__device__ float g_cos[SS*(DK/2)];
__device__ float g_sin[SS*(DK/2)];
// tf32 pre-converted operands
__device__ uint32_t g_xt[BB*SS*DMODEL];
__device__ uint32_t g_wqt[DMODEL*DMODEL];
__device__ uint32_t g_wkt[KVD*DMODEL];
__device__ uint32_t g_wvt[KVD*DMODEL];
__device__ uint32_t g_wot[DMODEL*DMODEL];
__device__ uint32_t g_attnt[BB*SS*DMODEL];   // attention output, tf32 words
// tf32 pre-converted, tile-interleaved K/V: 256 tiles x 4096 words each
__device__ uint32_t g_Kt[256*4096];
__device__ uint32_t g_Vt[256*4096];

// ---------------- helpers ----------------
__device__ __forceinline__ uint32_t f2tf(float x) {
    uint32_t r; asm("cvt.rna.tf32.f32 %0, %1;" : "=r"(r) : "f"(x)); return r;
}

__device__ __forceinline__ void mma_tf32(float* c, const uint32_t* a, const uint32_t* b) {
    asm volatile(
        "mma.sync.aligned.m16n8k8.row.col.f32.tf32.tf32.f32 "
        "{%0,%1,%2,%3}, {%4,%5,%6,%7}, {%8,%9}, {%0,%1,%2,%3};\n"
        : "+f"(c[0]), "+f"(c[1]), "+f"(c[2]), "+f"(c[3])
        : "r"(a[0]), "r"(a[1]), "r"(a[2]), "r"(a[3]), "r"(b[0]), "r"(b[1]));
}

__device__ __forceinline__ uint32_t smem_u32(const void* p) {
    uint32_t a;
    asm("{ .reg .u64 t; cvta.to.shared.u64 t, %1; cvt.u32.u64 %0, t; }" : "=r"(a) : "l"(p));
    return a;
}

__device__ __forceinline__ void cp16(uint32_t saddr, const void* g) {
    asm volatile("cp.async.cg.shared.global [%0], [%1], 16;" :: "r"(saddr), "l"(g));
}
#define CP_COMMIT() asm volatile("cp.async.commit_group;" ::: "memory")
#define CP_WAIT0()  asm volatile("cp.async.wait_group 0;" ::: "memory")

// Rope of one element at within-head column d of row base rp, seq position spos.
// Identical formula/order to the old rope_kernel -> bit-identical values.
__device__ __forceinline__ float rope_elem(const float* rp, int d, int spos) {
    int pr = d >> 1;
    float c  = g_cos[spos*32 + pr];
    float sn = g_sin[spos*32 + pr];
    float x1 = rp[d & ~1], x2 = rp[d | 1];
    return (d & 1) ? (x2*sn + x1*c) : (x1*c - x2*sn);
}

// ---------------- RoPE table ----------------
// theta_j = 1/(10000^(2j)/64); j>=5 -> inf -> theta=0 (fp32 overflow, matches ref)
__global__ void freq_rope_kernel(float* __restrict__ cosT, float* __restrict__ sinT) {
    int idx = blockIdx.x * blockDim.x + threadIdx.x;
    if (idx >= SS * (DK/2)) return;
    int s = idx / (DK/2);
    int j = idx % (DK/2);
    float p = powf(10000.0f, 2.0f * (float)j);
    float theta = 1.0f / (p / (float)DK);
    float ang = (float)s * theta;
    double a = (double)ang;
    cosT[idx] = (float)cos(a);
    sinT[idx] = (float)sin(a);
}

// ---------------- prep: x + weights -> tf32 gmem -----------------------------
#define NXT (BB*SS*DMODEL)          // 4194304
#define NWQ (DMODEL*DMODEL)         // 1048576
#define NWK (KVD*DMODEL)            // 262144
#define PREP_W_TOTAL (NXT + NWQ + 2*NWK + NWQ)   // 6815744

__global__ void prep_w(const float* __restrict__ x,
                       const float* __restrict__ wq, const float* __restrict__ wk,
                       const float* __restrict__ wv, const float* __restrict__ wo) {
    int idx = blockIdx.x * blockDim.x + threadIdx.x;
    if (idx < NXT) { g_xt[idx] = f2tf(x[idx]); return; }
    idx -= NXT;
    if (idx < NWQ) { g_wqt[idx] = f2tf(wq[idx]); return; }
    idx -= NWQ;
    if (idx < NWK) { g_wkt[idx] = f2tf(wk[idx]); return; }
    idx -= NWK;
    if (idx < NWK) { g_wvt[idx] = f2tf(wv[idx]); return; }
    idx -= NWK;
    g_wot[idx] = f2tf(wo[idx]);
}

// ---------------- prep: K/V -> tf32, tile-interleaved gmem, K-rope fused -----
// K tile (dense 64 words/row): w = (kk>>1)*16 + q*4 + (kk&1)*2 + h
//   <-> rope(K)[row][kk*8 + q + 4h]
// V tile (dense 128 words/slot): w = (n>>1)*32 + r1*4 + (n&1)*2 + h
//   <-> V[key][n*8 + r1] with PERMUTED key = (slot>>2)*8 + 2*(slot&3) + h.
__global__ void prep_kv() {
    int idx = blockIdx.x * blockDim.x + threadIdx.x;
    const int NK = 256*4096;
    if (idx < NK) {
        int w = idx & 63, row = (idx >> 6) & 63, tile = (idx >> 12) & 31;
        int kvh = (idx >> 17) & 3, b = idx >> 19;
        int kk2 = w >> 4, rem = w & 15;
        int q = rem >> 2, t = rem & 3;
        int kk = kk2*2 + (t >> 1), h = t & 1;
        int col = kk*8 + q + 4*h;
        int spos = tile*64 + row;
        const float* rp = &g_K[((size_t)(b*SS + spos))*KVD + kvh*DK];
        g_Kt[idx] = f2tf(rope_elem(rp, col, spos));
    } else {
        int j = idx - NK;
        int w = j & 127, slot = (j >> 7) & 31, tile = (j >> 12) & 31;
        int kvh = (j >> 17) & 3, b = j >> 19;
        int n2 = w >> 5, rem = w & 31;
        int r1v = rem >> 2, t = rem & 3;
        int n = n2*2 + (t >> 1), h = t & 1;
        int d = n*8 + r1v;
        int k = (slot >> 2)*8 + 2*(slot & 3) + h;   // permuted key mapping
        float v = g_V[((size_t)(b*SS + tile*64 + k))*KVD + kvh*DK + d];
        g_Vt[j] = f2tf(v);
    }
}

// ---------------- tf32 GEMM: cp.async staging of pre-converted operands ------
#define GST 20

__device__ __forceinline__ void gemm_body(
        const uint32_t* __restrict__ A, const uint32_t* __restrict__ W,
        const float* __restrict__ bias, float* __restrict__ C,
        int N, int Kd, int rowbase, int colbase) {
    __shared__ uint32_t As[2][128*GST];
    __shared__ uint32_t Bs[2][128*GST];
    uint32_t smbA = smem_u32(As);
    uint32_t smbB = smem_u32(Bs);
    int tid = threadIdx.x;
    int lane = tid & 31, warp = tid >> 5;
    int wm = warp >> 2, wn = warp & 3;

    float acc[4][4][4];
#pragma unroll
    for (int a = 0; a < 4; a++)
#pragma unroll
        for (int b = 0; b < 4; b++)
#pragma unroll
            for (int c = 0; c < 4; c++) acc[a][b][c] = 0.0f;

    int lr = tid >> 2;
    int kc = (tid & 3) * 4;

    const uint32_t* Arow0 = &A[(size_t)(rowbase + lr)*Kd + kc];
    const uint32_t* Arow1 = &A[(size_t)(rowbase + lr + 64)*Kd + kc];
    const uint32_t* Wrow0 = &W[(size_t)(colbase + lr)*Kd + kc];
    const uint32_t* Wrow1 = &W[(size_t)(colbase + lr + 64)*Kd + kc];
    uint32_t dA0 = smbA + (lr*GST + kc)*4;
    uint32_t dA1 = smbA + ((lr+64)*GST + kc)*4;
    uint32_t dB0 = smbB + (lr*GST + kc)*4;
    uint32_t dB1 = smbB + ((lr+64)*GST + kc)*4;
    const uint32_t SOFF = 128*GST*4;

    // prefetch k-tile 0
    cp16(dA0, Arow0); cp16(dA1, Arow1);
    cp16(dB0, Wrow0); cp16(dB1, Wrow1);
    CP_COMMIT();
    CP_WAIT0();
    __syncthreads();

    int nk = Kd / 16;
    for (int t = 0; t < nk; t++) {
        int s = t & 1;
        if (t + 1 < nk) {
            int kb = (t+1)*16;
            uint32_t so = (s^1) ? SOFF : 0;
            cp16(dA0 + so, Arow0 + kb); cp16(dA1 + so, Arow1 + kb);
            cp16(dB0 + so, Wrow0 + kb); cp16(dB1 + so, Wrow1 + kb);
            CP_COMMIT();
        }
#pragma unroll
        for (int ks = 0; ks < 2; ks++) {
            int k0 = ks * 8;
            uint32_t af[4][4], bf[4][2];
#pragma unroll
            for (int mi = 0; mi < 4; mi++) {
                int row = wm*64 + mi*16 + (lane >> 2);
                const uint32_t* p = &As[s][row*GST + k0 + (lane & 3)];
                af[mi][0] = p[0];
                af[mi][1] = p[8*GST];
                af[mi][2] = p[4];
                af[mi][3] = p[8*GST + 4];
            }
#pragma unroll
            for (int ni = 0; ni < 4; ni++) {
                int col = wn*32 + ni*8 + (lane >> 2);
                const uint32_t* p = &Bs[s][col*GST + k0 + (lane & 3)];
                bf[ni][0] = p[0];
                bf[ni][1] = p[4];
            }
#pragma unroll
            for (int mi = 0; mi < 4; mi++)
#pragma unroll
                for (int ni = 0; ni < 4; ni++)
                    mma_tf32(acc[mi][ni], af[mi], bf[ni]);
        }
        if (t + 1 < nk) CP_WAIT0();
        __syncthreads();
    }

#pragma unroll
    for (int mi = 0; mi < 4; mi++) {
        int row = rowbase + wm*64 + mi*16 + (lane >> 2);
#pragma unroll
        for (int ni = 0; ni < 4; ni++) {
            int col = colbase + wn*32 + ni*8 + 2*(lane & 3);
            float c0 = bias[col], c1 = bias[col+1];
            float2 v0 = {acc[mi][ni][0] + c0, acc[mi][ni][1] + c1};
            *(float2*)&C[(size_t)row*N + col] = v0;
            float2 v1 = {acc[mi][ni][2] + c0, acc[mi][ni][3] + c1};
            *(float2*)&C[(size_t)(row+8)*N + col] = v1;
        }
    }
}

// Fused Q+K+V projection (384 CTAs). Writes RAW (un-roped) Q/K; rope is
// applied by the consumers (attn prologue / prep_kv).
__global__ void __launch_bounds__(256) gemm_qkv(
        const float* __restrict__ bq, const float* __restrict__ bk,
        const float* __restrict__ bv) {
    int id = blockIdx.x;
    const uint32_t* W; const float* bias; float* C;
    int N, rowbase, colbase;
    if (id < 256) {
        W = g_wqt; bias = bq; C = g_Q; N = DMODEL;
        rowbase = (id >> 3) * 128; colbase = (id & 7) * 128;
    } else if (id < 320) {
        int i = id - 256;
        W = g_wkt; bias = bk; C = g_K; N = KVD;
        rowbase = (i >> 1) * 128; colbase = (i & 1) * 128;
    } else {
        int i = id - 320;
        W = g_wvt; bias = bv; C = g_V; N = KVD;
        rowbase = (i >> 1) * 128; colbase = (i & 1) * 128;
    }
    gemm_body(g_xt, W, bias, C, N, DMODEL, rowbase, colbase);
}

// Output projection (A = attention output, already tf32).
__global__ void __launch_bounds__(256) gemm_o(
        const float* __restrict__ bias, float* __restrict__ C) {
    gemm_body(g_attnt, g_wot, bias, C, DMODEL, DMODEL, blockIdx.y*128, blockIdx.x*128);
}

// ---------------- flash attention: paired q-tiles, uniform 33-step CTAs ------
// grid (16, 16): CTA x processes q-tile (31-x) then q-tile (x) -> every CTA
// does exactly 33 tile-steps; 256 uniform CTAs = one balanced wave.
// Per-q-tile computation identical to R16 -> bit-identical output.
#define KP_ST 80
#define VP_ST 136
#define STAGE_W (64*KP_ST + 32*VP_ST)      // 9472 words
#define ATT_SMEM (2*STAGE_W*4)             // 75776 bytes

__device__ __forceinline__ void issue_tile(uint32_t dstK, uint32_t dstV,
                                           const uint32_t* Kt, const uint32_t* Vt,
                                           int kt, int tid) {
    const char* srcK = (const char*)(Kt + (size_t)kt*4096);
    const char* srcV = (const char*)(Vt + (size_t)kt*4096);
#pragma unroll
    for (int i = 0; i < 4; i++) {
        int c = tid + 256*i;
        cp16(dstK + (c >> 4)*(KP_ST*4) + (c & 15)*16, srcK + c*16);
        cp16(dstV + (c >> 5)*(VP_ST*4) + (c & 31)*16, srcV + c*16);
    }
    CP_COMMIT();
}

__global__ void __launch_bounds__(256, 2) attn_tf32() {
    extern __shared__ uint32_t smA[];
    uint32_t smb = smem_u32(smA);

    int tid = threadIdx.x, lane = tid & 31, warp = tid >> 5;
    int g = warp >> 2, sub = warp & 3;
    int y = blockIdx.y;
    int b = y >> 3, kvh = (y >> 1) & 3, hg = y & 1;
    int h = kvh*4 + hg*2 + g;

    const float* Qb = g_Q + (size_t)b*SS*DMODEL + h*DK;
    const uint32_t* Ktb = g_Kt + (size_t)((b*4 + kvh)*32)*4096;
    const uint32_t* Vtb = g_Vt + (size_t)((b*4 + kvh)*32)*4096;
    int r1 = lane >> 2;
    int q  = lane & 3;
    int qrow = 16*sub + r1;

    for (int half = 0; half < 2; half++) {
        int qt = half ? (int)blockIdx.x : 31 - (int)blockIdx.x;
        int q0 = qt * 64;

        // Q fragments: rope applied inline, then pre-scaled by 1/sqrt(64)
        uint32_t qf[8][4];
        {
            int s0 = q0 + qrow, s8 = s0 + 8;
            const float* rp0 = &Qb[(size_t)s0*DMODEL];
            const float* rp8 = &Qb[(size_t)s8*DMODEL];
#pragma unroll
            for (int kk = 0; kk < 8; kk++) {
                int d = kk*8 + q;
                qf[kk][0] = f2tf(rope_elem(rp0, d,     s0) * 0.125f);
                qf[kk][1] = f2tf(rope_elem(rp8, d,     s8) * 0.125f);
                qf[kk][2] = f2tf(rope_elem(rp0, d + 4, s0) * 0.125f);
                qf[kk][3] = f2tf(rope_elem(rp8, d + 4, s8) * 0.125f);
            }
        }

        float m1 = -1e30f, m2 = -1e30f, l1 = 0.0f, l2 = 0.0f;
        float of[8][4];
#pragma unroll
        for (int n = 0; n < 8; n++)
#pragma unroll
            for (int j = 0; j < 4; j++) of[n][j] = 0.0f;

        // prefetch tile 0 directly into stage 0
        issue_tile(smb, smb + 64*KP_ST*4, Ktb, Vtb, 0, tid);
        CP_WAIT0();
        __syncthreads();

        for (int kt = 0; kt <= qt; kt++) {
            int s = kt & 1;
            const uint32_t* Kp = smA + s*STAGE_W;
            const uint32_t* Vp = Kp + 64*KP_ST;

            // issue cp.async for next tile into the other stage
            if (kt < qt) {
                uint32_t dst = smb + (s^1)*STAGE_W*4;
                issue_tile(dst, dst + 64*KP_ST*4, Ktb, Vtb, kt+1, tid);
            }

            // S = (Q/8) K^T   (LDS.128 = 2 B-frags; per-acc kk order 0..7)
            float sf[8][4];
#pragma unroll
            for (int n = 0; n < 8; n++)
#pragma unroll
                for (int j = 0; j < 4; j++) sf[n][j] = 0.0f;
#pragma unroll
            for (int kk2 = 0; kk2 < 4; kk2++) {
#pragma unroll
                for (int n = 0; n < 8; n++) {
                    int key = n*8 + r1;
                    uint4 b4 = *(const uint4*)&Kp[key*KP_ST + kk2*16 + q*4];
                    uint32_t bf0[2] = {b4.x, b4.y};
                    mma_tf32(sf[n], qf[2*kk2], bf0);
                    uint32_t bf1[2] = {b4.z, b4.w};
                    mma_tf32(sf[n], qf[2*kk2+1], bf1);
                }
            }

            // causal mask on diagonal tile
            if (kt == qt) {
#pragma unroll
                for (int n = 0; n < 8; n++) {
                    int col = n*8 + 2*q;
                    if (col     > qrow)     sf[n][0] = -1e30f;
                    if (col + 1 > qrow)     sf[n][1] = -1e30f;
                    if (col     > qrow + 8) sf[n][2] = -1e30f;
                    if (col + 1 > qrow + 8) sf[n][3] = -1e30f;
                }
            }

            // online softmax
            float mx1 = -1e30f, mx2 = -1e30f;
#pragma unroll
            for (int n = 0; n < 8; n++) {
                mx1 = fmaxf(mx1, fmaxf(sf[n][0], sf[n][1]));
                mx2 = fmaxf(mx2, fmaxf(sf[n][2], sf[n][3]));
            }
            mx1 = fmaxf(mx1, __shfl_xor_sync(0xffffffffu, mx1, 1));
            mx1 = fmaxf(mx1, __shfl_xor_sync(0xffffffffu, mx1, 2));
            mx2 = fmaxf(mx2, __shfl_xor_sync(0xffffffffu, mx2, 1));
            mx2 = fmaxf(mx2, __shfl_xor_sync(0xffffffffu, mx2, 2));
            float mn1 = fmaxf(m1, mx1), mn2 = fmaxf(m2, mx2);
            float c1 = __expf(m1 - mn1), c2 = __expf(m2 - mn2);
            float s1 = 0.0f, s2 = 0.0f;
#pragma unroll
            for (int n = 0; n < 8; n++) {
                sf[n][0] = __expf(sf[n][0] - mn1);
                sf[n][1] = __expf(sf[n][1] - mn1);
                sf[n][2] = __expf(sf[n][2] - mn2);
                sf[n][3] = __expf(sf[n][3] - mn2);
                s1 += sf[n][0] + sf[n][1];
                s2 += sf[n][2] + sf[n][3];
            }
            s1 += __shfl_xor_sync(0xffffffffu, s1, 1);
            s1 += __shfl_xor_sync(0xffffffffu, s1, 2);
            s2 += __shfl_xor_sync(0xffffffffu, s2, 1);
            s2 += __shfl_xor_sync(0xffffffffu, s2, 2);
            l1 = l1*c1 + s1;  l2 = l2*c2 + s2;
            m1 = mn1;         m2 = mn2;
#pragma unroll
            for (int n = 0; n < 8; n++) {
                of[n][0] *= c1; of[n][1] *= c1;
                of[n][2] *= c2; of[n][3] *= c2;
            }

            // O += P V ; A-frag = OWN registers (V key-permuted), no transpose
#pragma unroll
            for (int kk = 0; kk < 8; kk++) {
                uint32_t pa[4];
                pa[0] = f2tf(sf[kk][0]);   // P[qrow  ][key 2q  ]
                pa[1] = f2tf(sf[kk][2]);   // P[qrow+8][key 2q  ]
                pa[2] = f2tf(sf[kk][1]);   // P[qrow  ][key 2q+1]
                pa[3] = f2tf(sf[kk][3]);   // P[qrow+8][key 2q+1]
                int slot = kk*4 + q;
#pragma unroll
                for (int n2 = 0; n2 < 4; n2++) {
                    uint4 v4 = *(const uint4*)&Vp[slot*VP_ST + n2*32 + r1*4];
                    uint32_t vb0[2] = {v4.x, v4.y};
                    mma_tf32(of[2*n2], pa, vb0);
                    uint32_t vb1[2] = {v4.z, v4.w};
                    mma_tf32(of[2*n2+1], pa, vb1);
                }
            }

            // next stage: own copies done + barrier makes all copies visible
            if (kt < qt) CP_WAIT0();
            __syncthreads();
        }

        float inv1 = 1.0f / l1, inv2 = 1.0f / l2;
        uint32_t* Ot = g_attnt + (size_t)b*SS*DMODEL + h*DK;
#pragma unroll
        for (int n = 0; n < 8; n++) {
            int col = n*8 + 2*q;
            uint2 w0 = {f2tf(of[n][0]*inv1), f2tf(of[n][1]*inv1)};
            *(uint2*)&Ot[(size_t)(q0 + qrow)*DMODEL + col] = w0;
            uint2 w1 = {f2tf(of[n][2]*inv2), f2tf(of[n][3]*inv2)};
            *(uint2*)&Ot[(size_t)(q0 + qrow + 8)*DMODEL + col] = w1;
        }
    }
}

// ---------------- launch ----------------
extern "C" void kernel_launch(void* const* d_in, const int* in_sizes, int n_in,
                              void* d_out, int out_size) {
    const float* x  = (const float*)d_in[0];
    const float* wq = (const float*)d_in[1];
    const float* bq = (const float*)d_in[2];
    const float* wk = (const float*)d_in[3];
    const float* bk = (const float*)d_in[4];
    const float* wv = (const float*)d_in[5];
    const float* bv = (const float*)d_in[6];
    const float* wo = (const float*)d_in[7];
    const float* bo = (const float*)d_in[8];
    float* out = (float*)d_out;

    float *cT, *sT;
    cudaGetSymbolAddress((void**)&cT, g_cos);
    cudaGetSymbolAddress((void**)&sT, g_sin);

    static int cfg_done = 0;
    if (!cfg_done) {
        cudaFuncSetAttribute(attn_tf32, cudaFuncAttributeMaxDynamicSharedMemorySize, ATT_SMEM);
        cfg_done = 1;
    }

    // RoPE tables + operand pre-conversion (independent)
    freq_rope_kernel<<<(SS*(DK/2) + 255)/256, 256>>>(cT, sT);
    prep_w<<<(PREP_W_TOTAL + 255)/256, 256>>>(x, wq, wk, wv, wo);

    // fused Q+K+V projections (one launch; Q/K written un-roped)
    gemm_qkv<<<384, 256>>>(bq, bk, bv);

    // pre-convert K/V to tf32 tile-interleaved layouts (K-rope fused)
    prep_kv<<<(2*256*4096)/256, 256>>>();

    // attention: paired q-tiles, 256 uniform CTAs, one wave
    attn_tf32<<<dim3(16, BB*HKV*2), 256, ATT_SMEM>>>();

    // output projection
    gemm_o<<<dim3(DMODEL/128, BB*SS/128), 256>>>(bo, out);
}